// round 4
// baseline (speedup 1.0000x reference)
#include <cuda_runtime.h>
#include <math.h>

#define U_N 4000
#define P_N 4000
#define G_N 200
#define D   64
#define B_N 512
#define NUP (U_N + P_N)   // 8000
#define NGU (G_N + U_N)   // 4200
#define NGP (G_N + P_N)   // 4200
#define NTOT (NUP + NGU + NGP)

// ---------------- scratch (device globals; no allocation allowed) ----------
__device__ float g_Xup[NUP * D];
__device__ float g_Xgu[NGU * D];
__device__ float g_Xgp[NGP * D];
__device__ float g_Rup[NUP * D];
__device__ float g_Rgu[NGU * D];
__device__ float g_Rgp[NGP * D];
__device__ float g_deg[NTOT];

// ---------------- init: zero accumulators + build concatenated X -----------
__global__ void init_all(const float* __restrict__ ue,
                         const float* __restrict__ pe,
                         const float* __restrict__ ge)
{
    int i = blockIdx.x * blockDim.x + threadIdx.x;
    if (i < NUP * D) {
        g_Rup[i] = 0.f;
        g_Xup[i] = (i < U_N * D) ? ue[i] : pe[i - U_N * D];
    }
    if (i < NGU * D) {
        g_Rgu[i] = 0.f;
        g_Rgp[i] = 0.f;
        g_Xgu[i] = (i < G_N * D) ? ge[i] : ue[i - G_N * D];
        g_Xgp[i] = (i < G_N * D) ? ge[i] : pe[i - G_N * D];
    }
    if (i < NTOT) g_deg[i] = 0.f;
}

// ---------------- cp.async helpers -----------------------------------------
__device__ __forceinline__ void cp_async16(void* smem_dst, const void* gmem_src, int src_bytes)
{
    unsigned saddr = (unsigned)__cvta_generic_to_shared(smem_dst);
    asm volatile("cp.async.cg.shared.global [%0], [%1], 16, %2;\n"
                 :: "r"(saddr), "l"(gmem_src), "r"(src_bytes));
}
__device__ __forceinline__ void cp_commit() { asm volatile("cp.async.commit_group;\n"); }
template<int N> __device__ __forceinline__ void cp_wait()
{ asm volatile("cp.async.wait_group %0;\n" :: "n"(N)); }

__device__ __forceinline__ void mma_tf32(
    float& c0, float& c1, float& c2, float& c3,
    unsigned a0, unsigned a1, unsigned a2, unsigned a3,
    unsigned b0, unsigned b1)
{
    asm volatile(
        "mma.sync.aligned.m16n8k8.row.col.f32.tf32.tf32.f32 "
        "{%0,%1,%2,%3}, {%4,%5,%6,%7}, {%8,%9}, {%0,%1,%2,%3};\n"
        : "+f"(c0), "+f"(c1), "+f"(c2), "+f"(c3)
        : "r"(a0), "r"(a1), "r"(a2), "r"(a3), "r"(b0), "r"(b1));
}

// ---------------- fused tf32 MMA propagation GEMM ---------------------------
// R += A@X (tf32 MMA), deg += rowsum(A); three problems in one grid.
// Tile: BM=256 x 64, BK=32. 8 warps as 4M x 2N; warp = 64 rows x 32 cols.
#define BM 256
#define BK 32
#define ASTRIDE 36
#define XSTRIDE 72
#define ASZ (BM * ASTRIDE)          // 9216 floats
#define XSZ (BK * XSTRIDE)          // 2304 floats
#define STAGE (ASZ + XSZ)           // 11520 floats
#define SMEM_BYTES (2 * STAGE * 4)  // 92160 B

#define RT0 32
#define RT12 17
#define KS0 16
#define KS12 8
#define NB0 (RT0 * KS0)       // 512
#define NB12 (RT12 * KS12)    // 136
#define NBLK (NB0 + 2 * NB12) // 784

__device__ __forceinline__ void load_tiles(
    float* As, float* Xs, const float* __restrict__ A, const float* __restrict__ X,
    int n, int rowBase, int k0, int tid)
{
    // A tile: 256 x 32 floats = 2048 float4 slots, 8 per thread
    #pragma unroll
    for (int i = 0; i < 8; i++) {
        int slot = tid + i * 256;
        int r  = slot >> 3;
        int c4 = (slot & 7) << 2;
        int gr = rowBase + r;
        int gc = k0 + c4;
        float* dst = &As[r * ASTRIDE + c4];
        int rem = n - gc;           // n multiple of 4
        int bytes = (gr < n) ? ((rem >= 4) ? 16 : (rem > 0 ? rem * 4 : 0)) : 0;
        if (bytes > 0) {
            cp_async16(dst, &A[(size_t)gr * n + gc], bytes);
        } else {
            *reinterpret_cast<float4*>(dst) = make_float4(0.f, 0.f, 0.f, 0.f);
        }
    }
    // X tile: 32 x 64 floats = 512 float4 slots, 2 per thread
    #pragma unroll
    for (int i = 0; i < 2; i++) {
        int slot = tid + i * 256;
        int kr = slot >> 4;
        int c4 = (slot & 15) << 2;
        int gk = k0 + kr;
        float* dst = &Xs[kr * XSTRIDE + c4];
        if (gk < n) {
            cp_async16(dst, &X[(size_t)gk * D + c4], 16);
        } else {
            *reinterpret_cast<float4*>(dst) = make_float4(0.f, 0.f, 0.f, 0.f);
        }
    }
}

extern "C" __global__ __launch_bounds__(256)
void gemm_all(const float* __restrict__ A0, const float* __restrict__ A1,
              const float* __restrict__ A2,
              const float* __restrict__ X0, const float* __restrict__ X1,
              const float* __restrict__ X2,
              float* __restrict__ R0, float* __restrict__ R1, float* __restrict__ R2,
              float* __restrict__ degAll)
{
    extern __shared__ float smem[];
    const int tid   = threadIdx.x;
    const int lane  = tid & 31;
    const int warp  = tid >> 5;
    const int warpM = warp >> 1;
    const int warpN = warp & 1;
    const int wr    = warpM * 64;
    const int kc    = lane & 3;
    const int rq    = lane >> 2;

    // ---- map block -> (problem, rowTile, ksplit) ----
    const float *A, *X; float *R, *deg;
    int n, rowTiles, kIters, kps, local;
    int b = blockIdx.x;
    if (b < NB0)              { A = A0; X = X0; R = R0; deg = degAll;             n = NUP; rowTiles = RT0;  kIters = 250; kps = 16; local = b; }
    else if (b < NB0 + NB12)  { A = A1; X = X1; R = R1; deg = degAll + NUP;       n = NGU; rowTiles = RT12; kIters = 132; kps = 17; local = b - NB0; }
    else                      { A = A2; X = X2; R = R2; deg = degAll + NUP + NGU; n = NGP; rowTiles = RT12; kIters = 132; kps = 17; local = b - NB0 - NB12; }

    const int rowTile = local % rowTiles;
    const int split   = local / rowTiles;
    const int rowBase = rowTile * BM;
    const int itStart = split * kps;
    const int itEnd   = min(kIters, itStart + kps);
    const int nIt     = itEnd - itStart;
    if (nIt <= 0) return;

    float* As[2] = { smem,       smem + STAGE };
    float* Xs[2] = { smem + ASZ, smem + STAGE + ASZ };

    float c[4][4][4];
    #pragma unroll
    for (int mt = 0; mt < 4; mt++)
        #pragma unroll
        for (int nt = 0; nt < 4; nt++)
            #pragma unroll
            for (int j = 0; j < 4; j++) c[mt][nt][j] = 0.f;

    float dacc[4][2];
    #pragma unroll
    for (int mt = 0; mt < 4; mt++) { dacc[mt][0] = 0.f; dacc[mt][1] = 0.f; }

    load_tiles(As[0], Xs[0], A, X, n, rowBase, itStart * BK, tid);
    cp_commit();

    for (int i = 0; i < nIt; i++) {
        int cur = i & 1;
        if (i + 1 < nIt)
            load_tiles(As[cur ^ 1], Xs[cur ^ 1], A, X, n, rowBase, (itStart + i + 1) * BK, tid);
        cp_commit();
        cp_wait<1>();
        __syncthreads();

        const float* Ac = As[cur];
        const float* Xc = Xs[cur];

        #pragma unroll
        for (int ks = 0; ks < 4; ks++) {
            int kb = ks * 8;
            unsigned a[4][4];
            #pragma unroll
            for (int mt = 0; mt < 4; mt++) {
                int base = (wr + mt * 16 + rq) * ASTRIDE + kb + kc;
                a[mt][0] = __float_as_uint(Ac[base]);
                a[mt][1] = __float_as_uint(Ac[base + 8 * ASTRIDE]);
                a[mt][2] = __float_as_uint(Ac[base + 4]);
                a[mt][3] = __float_as_uint(Ac[base + 8 * ASTRIDE + 4]);
                dacc[mt][0] += __uint_as_float(a[mt][0]) + __uint_as_float(a[mt][2]);
                dacc[mt][1] += __uint_as_float(a[mt][1]) + __uint_as_float(a[mt][3]);
            }
            #pragma unroll
            for (int nt = 0; nt < 4; nt++) {
                int col = warpN * 32 + nt * 8 + rq;
                unsigned b0 = __float_as_uint(Xc[(kb + kc)     * XSTRIDE + col]);
                unsigned b1 = __float_as_uint(Xc[(kb + kc + 4) * XSTRIDE + col]);
                #pragma unroll
                for (int mt = 0; mt < 4; mt++)
                    mma_tf32(c[mt][nt][0], c[mt][nt][1], c[mt][nt][2], c[mt][nt][3],
                             a[mt][0], a[mt][1], a[mt][2], a[mt][3], b0, b1);
            }
        }
        __syncthreads();
    }

    // ---- deg: reduce over the 4 kc lanes, one atomic per row (warpN==0 only
    //      would halve traffic but warpN also holds distinct kc partials; each
    //      A element was loaded by exactly one warp, so both warpN columns of
    //      a row... rows are owned by warpM only; warpN duplicates A loads!
    //      -> scale by 0.5 is WRONG; instead only warpN==0 contributes? No:
    //      both warpN warps loaded the same A fragments, so divide by 2. ----
    // NOTE: warps with same warpM but different warpN load identical A frags.
    #pragma unroll
    for (int mt = 0; mt < 4; mt++)
        #pragma unroll
        for (int h = 0; h < 2; h++) {
            float v = dacc[mt][h];
            v += __shfl_xor_sync(0xffffffffu, v, 1);
            v += __shfl_xor_sync(0xffffffffu, v, 2);
            if (warpN == 0 && (lane & 3) == 0) {
                int gr = rowBase + wr + mt * 16 + h * 8 + rq;
                if (gr < n) atomicAdd(&deg[gr], v);
            }
        }

    #pragma unroll
    for (int mt = 0; mt < 4; mt++) {
        int r0 = rowBase + wr + mt * 16 + rq;
        #pragma unroll
        for (int nt = 0; nt < 4; nt++) {
            int cc = warpN * 32 + nt * 8 + (lane & 3) * 2;
            if (r0 < n) {
                atomicAdd(&R[r0 * D + cc],     c[mt][nt][0]);
                atomicAdd(&R[r0 * D + cc + 1], c[mt][nt][1]);
            }
            if (r0 + 8 < n) {
                atomicAdd(&R[(r0 + 8) * D + cc],     c[mt][nt][2]);
                atomicAdd(&R[(r0 + 8) * D + cc + 1], c[mt][nt][3]);
            }
        }
    }
}

// ---------------- epilogue: R = (X + R/max(deg,1e-8)) * 0.5 (all 3) --------
__global__ void epilogue_all()
{
    int idx = blockIdx.x * blockDim.x + threadIdx.x;
    if (idx >= NTOT * D) return;
    int row = idx >> 6;
    float d = fmaxf(g_deg[row], 1e-8f);
    if (row < NUP) {
        g_Rup[idx] = (g_Xup[idx] + g_Rup[idx] / d) * 0.5f;
    } else if (row < NUP + NGU) {
        int j = idx - NUP * D;
        g_Rgu[j] = (g_Xgu[j] + g_Rgu[j] / d) * 0.5f;
    } else {
        int j = idx - (NUP + NGU) * D;
        g_Rgp[j] = (g_Xgp[j] + g_Rgp[j] / d) * 0.5f;
    }
}

// ---------------- fused attention score kernel (tf32 MMA) -------------------
// Block: 64 users x 64 papers. Gathers uf, computes q = uf@W in-block,
// then 4 GEMM products via mma, combines with 2-way softmax.
#define SSTR 68
#define S_SMEM_FLOATS (4 * 64 * SSTR + 64 * 64)
#define S_SMEM_BYTES  (S_SMEM_FLOATS * 4)      // 86016

extern "C" __global__ __launch_bounds__(256)
void score_all(const int* __restrict__ uids, const float* __restrict__ W,
               float* __restrict__ scores, float* __restrict__ out_uf)
{
    extern __shared__ float smem[];
    float* UFs = smem;               // 64 x SSTR
    float* Qs  = UFs + 64 * SSTR;
    float* I0s = Qs  + 64 * SSTR;
    float* I1s = I0s + 64 * SSTR;
    float* Ws  = I1s + 64 * SSTR;    // 64 x 64

    const int tid   = threadIdx.x;
    const int lane  = tid & 31;
    const int warp  = tid >> 5;
    const int warpB = warp >> 1;     // 4 groups of 16 users
    const int warpP = warp & 1;      // 2 groups of 32 papers
    const int kc    = lane & 3;
    const int rq    = lane >> 2;
    const int ub    = blockIdx.y * 64;
    const int pb    = blockIdx.x * 64;

    // async-load I tiles (row-major [paper][k])
    #pragma unroll
    for (int i = 0; i < 4; i++) {
        int slot = tid + i * 256;    // 1024 slots per matrix
        int p  = slot >> 4;
        int c4 = (slot & 15) << 2;
        int gp = pb + p;
        if (gp < P_N) {
            cp_async16(&I0s[p * SSTR + c4], &g_Rup[(size_t)(U_N + gp) * D + c4], 16);
            cp_async16(&I1s[p * SSTR + c4], &g_Rgp[(size_t)(G_N + gp) * D + c4], 16);
        } else {
            *reinterpret_cast<float4*>(&I0s[p * SSTR + c4]) = make_float4(0.f, 0.f, 0.f, 0.f);
            *reinterpret_cast<float4*>(&I1s[p * SSTR + c4]) = make_float4(0.f, 0.f, 0.f, 0.f);
        }
    }
    cp_commit();

    // gather uf + load W
    for (int i = tid; i < 64 * D; i += 256) {
        int u = i >> 6, d = i & 63;
        int uid = uids[ub + u];
        float v = 0.5f * (g_Rup[(size_t)uid * D + d] + g_Rgu[(size_t)(G_N + uid) * D + d]);
        UFs[u * SSTR + d] = v;
        if (blockIdx.x == 0) out_uf[(size_t)(ub + u) * D + d] = v;
        Ws[i] = W[i];
    }
    __syncthreads();

    // q = uf @ W  (thread: row r, 16 output dims)
    {
        int r  = tid >> 2;
        int dg = (tid & 3) << 4;
        float qa[16];
        #pragma unroll
        for (int j = 0; j < 16; j++) qa[j] = 0.f;
        for (int k = 0; k < D; k++) {
            float ufv = UFs[r * SSTR + k];
            const float4* wrow = reinterpret_cast<const float4*>(&Ws[k * D + dg]);
            #pragma unroll
            for (int j4 = 0; j4 < 4; j4++) {
                float4 w = wrow[j4];
                qa[j4 * 4 + 0] += ufv * w.x;
                qa[j4 * 4 + 1] += ufv * w.y;
                qa[j4 * 4 + 2] += ufv * w.z;
                qa[j4 * 4 + 3] += ufv * w.w;
            }
        }
        #pragma unroll
        for (int j = 0; j < 16; j++) Qs[r * SSTR + dg + j] = qa[j];
    }
    cp_wait<0>();
    __syncthreads();

    float l0[4][4] = {}, l1[4][4] = {}, d0[4][4] = {}, d1[4][4] = {};

    #pragma unroll
    for (int ks = 0; ks < 8; ks++) {
        int kb = ks * 8;
        int abase = (warpB * 16 + rq) * SSTR + kb + kc;
        unsigned aq[4], au[4];
        aq[0] = __float_as_uint(Qs[abase]);
        aq[1] = __float_as_uint(Qs[abase + 8 * SSTR]);
        aq[2] = __float_as_uint(Qs[abase + 4]);
        aq[3] = __float_as_uint(Qs[abase + 8 * SSTR + 4]);
        au[0] = __float_as_uint(UFs[abase]);
        au[1] = __float_as_uint(UFs[abase + 8 * SSTR]);
        au[2] = __float_as_uint(UFs[abase + 4]);
        au[3] = __float_as_uint(UFs[abase + 8 * SSTR + 4]);
        #pragma unroll
        for (int nt = 0; nt < 4; nt++) {
            int nb = (warpP * 32 + nt * 8 + rq) * SSTR + kb + kc;
            unsigned b00 = __float_as_uint(I0s[nb]);
            unsigned b01 = __float_as_uint(I0s[nb + 4]);
            unsigned b10 = __float_as_uint(I1s[nb]);
            unsigned b11 = __float_as_uint(I1s[nb + 4]);
            mma_tf32(l0[nt][0], l0[nt][1], l0[nt][2], l0[nt][3], aq[0], aq[1], aq[2], aq[3], b00, b01);
            mma_tf32(l1[nt][0], l1[nt][1], l1[nt][2], l1[nt][3], aq[0], aq[1], aq[2], aq[3], b10, b11);
            mma_tf32(d0[nt][0], d0[nt][1], d0[nt][2], d0[nt][3], au[0], au[1], au[2], au[3], b00, b01);
            mma_tf32(d1[nt][0], d1[nt][1], d1[nt][2], d1[nt][3], au[0], au[1], au[2], au[3], b10, b11);
        }
    }

    const float scale = 0.125f;   // 1/sqrt(64)
    #pragma unroll
    for (int nt = 0; nt < 4; nt++) {
        #pragma unroll
        for (int j = 0; j < 4; j++) {
            int r = ub + warpB * 16 + rq + ((j >= 2) ? 8 : 0);
            int p = pb + warpP * 32 + nt * 8 + (lane & 3) * 2 + (j & 1);
            if (p < P_N) {
                float z  = (l0[nt][j] - l1[nt][j]) * scale;
                float a0 = 1.f / (1.f + expf(-z));
                scores[(size_t)r * P_N + p] = a0 * d0[nt][j] + (1.f - a0) * d1[nt][j];
            }
        }
    }
}

// ---------------- launch -----------------------------------------------------
extern "C" void kernel_launch(void* const* d_in, const int* in_sizes, int n_in,
                              void* d_out, int out_size)
{
    const float* A_up = (const float*)d_in[0];
    const float* A_gu = (const float*)d_in[1];
    const float* A_gp = (const float*)d_in[2];
    const float* ue   = (const float*)d_in[3];
    const float* pe   = (const float*)d_in[4];
    const float* ge   = (const float*)d_in[5];
    const float* W    = (const float*)d_in[6];
    const int*   uids = (const int*)d_in[7];
    float* out = (float*)d_out;

    float *pXup, *pXgu, *pXgp, *pRup, *pRgu, *pRgp, *pdeg;
    cudaGetSymbolAddress((void**)&pXup, g_Xup);
    cudaGetSymbolAddress((void**)&pXgu, g_Xgu);
    cudaGetSymbolAddress((void**)&pXgp, g_Xgp);
    cudaGetSymbolAddress((void**)&pRup, g_Rup);
    cudaGetSymbolAddress((void**)&pRgu, g_Rgu);
    cudaGetSymbolAddress((void**)&pRgp, g_Rgp);
    cudaGetSymbolAddress((void**)&pdeg, g_deg);

    cudaFuncSetAttribute(gemm_all,  cudaFuncAttributeMaxDynamicSharedMemorySize, SMEM_BYTES);
    cudaFuncSetAttribute(score_all, cudaFuncAttributeMaxDynamicSharedMemorySize, S_SMEM_BYTES);

    init_all<<<(NUP * D + 255) / 256, 256>>>(ue, pe, ge);

    gemm_all<<<NBLK, 256, SMEM_BYTES>>>(A_up, A_gu, A_gp,
                                        pXup, pXgu, pXgp,
                                        pRup, pRgu, pRgp, pdeg);

    epilogue_all<<<(NTOT * D + 255) / 256, 256>>>();

    dim3 sg((P_N + 63) / 64, B_N / 64);
    score_all<<<sg, 256, S_SMEM_BYTES>>>(uids, W, out, out + (size_t)B_N * P_N);
}